// round 15
// baseline (speedup 1.0000x reference)
#include <cuda_runtime.h>
#include <cuda_fp16.h>
#include <cstdint>

#define DIM    256
#define NE     8192
#define NROWS  32768
#define THRESH 0.04f
#define FLAG_CAP NROWS

// ---- device scratch ----
__device__ float  g_c[NE];                 // 0.5*||e_j||^2
__device__ float  g_cp[4][NE];             // norm partials (deterministic combine)
__device__ int    g_idx[NROWS];
__device__ float  g_eT[NE * DIM];          // fp32 transposed codebook (gather)
__device__ __half g_epk[NE * DIM];         // fp16 codebook, pre-packed MMA B-fragments
__device__ float  g_hb[2][NROWS];          // per code-half best
__device__ float  g_hs[2][NROWS];          // per code-half second
__device__ int    g_hi[2][NROWS];          // per code-half argbest
__device__ double g_diff;
__device__ int    g_nflag;
__device__ int    g_flag[FLAG_CAP];
__device__ unsigned long long g_rkey[FLAG_CAP];

__device__ __forceinline__ uint32_t smem_u32(const void* p) {
    uint32_t a;
    asm("{ .reg .u64 t; cvta.to.shared.u64 t, %1; cvt.u32.u64 %0, t; }" : "=r"(a) : "l"(p));
    return a;
}

__device__ __forceinline__ void ldmx4(uint32_t& r0, uint32_t& r1, uint32_t& r2, uint32_t& r3,
                                      uint32_t addr) {
    asm volatile("ldmatrix.sync.aligned.m8n8.x4.shared.b16 {%0,%1,%2,%3}, [%4];"
                 : "=r"(r0), "=r"(r1), "=r"(r2), "=r"(r3) : "r"(addr));
}

__device__ __forceinline__ void mma16816(float* c,
                                         const uint32_t* a,
                                         uint32_t b0, uint32_t b1) {
    asm volatile(
        "mma.sync.aligned.m16n8k16.row.col.f32.f16.f16.f32 "
        "{%0,%1,%2,%3}, {%4,%5,%6,%7}, {%8,%9}, {%0,%1,%2,%3};"
        : "+f"(c[0]), "+f"(c[1]), "+f"(c[2]), "+f"(c[3])
        : "r"(a[0]), "r"(a[1]), "r"(a[2]), "r"(a[3]), "r"(b0), "r"(b1));
}

// ============================================================
// Prep kernels
// ============================================================
__global__ void norms_part_kernel(const float* __restrict__ embed) {
    int j = blockIdx.x * 256 + threadIdx.x;
    int q = blockIdx.y;                    // dim quarter
    float s = 0.f;
    #pragma unroll 8
    for (int d = q * 64; d < q * 64 + 64; ++d) {
        float v = embed[(size_t)d * NE + j];
        s += v * v;
    }
    g_cp[q][j] = s;
}

__global__ void norms_comb_kernel() {
    int j = blockIdx.x * 256 + threadIdx.x;
    if (blockIdx.x == 0 && threadIdx.x == 0) { g_diff = 0.0; g_nflag = 0; }
    g_c[j] = 0.5f * (((g_cp[0][j] + g_cp[1][j]) + g_cp[2][j]) + g_cp[3][j]);
}

// Fused transpose (-> g_eT) + fp16 fragment pack (-> g_epk).
__global__ void transpose_pack_kernel(const float* __restrict__ embed) {
    __shared__ float t[32][33];
    int j0 = blockIdx.x * 32;
    int d0 = blockIdx.y * 32;
    int tx = threadIdx.x, ty = threadIdx.y;   // 32 x 8
    #pragma unroll
    for (int i = 0; i < 32; i += 8) {
        int d = d0 + ty + i;
        int j = j0 + tx;
        float v = embed[(size_t)d * NE + j];
        t[ty + i][tx] = v;
        int jt = j >> 7;
        int ncol = (j >> 6) & 1;
        int p = (j >> 3) & 7;
        int nl = j & 7;
        int g = d >> 5;
        int kk = d & 31;
        int l = nl * 4 + ((kk >> 1) & 3);
        int h = ((kk >> 3) << 1) + (kk & 1);
        size_t unit = ((size_t)(jt * 2 + ncol) * 8 + g) * 8 + p;
        g_epk[unit * 256 + l * 8 + h] = __float2half(v);
    }
    __syncthreads();
    #pragma unroll
    for (int i = 0; i < 32; i += 8)
        g_eT[(size_t)(j0 + ty + i) * DIM + (d0 + tx)] = t[tx][ty + i];
}

// ============================================================
// Main HMMA kernel: 128 threads (4 warps), 2048 CTAs.
// CTA = (row-block of 32) x (code HALF of 4096): 6.9 waves, ~1% tail.
// Warp: m32 x distinct 1024-code quarter of the half (128 u-steps).
// Inner loop identical to R12 except norms folded into accumulator init.
// Per-(half,row) results go to global scratch; merge_kernel finalizes.
// ============================================================
__global__ void __launch_bounds__(128, 2)
tc_argmin_kernel(const float* __restrict__ input) {
    __shared__ __align__(16) __half stage[8192];  // 16KB: 32-row A staging
    __shared__ float sbv[4][32];
    __shared__ float ssv[4][32];
    __shared__ int   sbi[4][32];

    const int tid  = threadIdx.x;
    const int wid  = tid >> 5;
    const int lane = tid & 31;
    const int half = blockIdx.x & 1;
    const int row0 = (blockIdx.x >> 1) * 32;
    const int mat  = lane >> 3;
    const int rr   = lane & 7;

    // ================= prologue: A fragments (both m16 tiles) ==============
    uint32_t areg[128];   // 2 m-tiles x 16 k16-chunks x 4
    {
        const int r = tid & 31;     // row
        const int p = tid >> 5;     // segment 0..3 (64 halves each)
        const float4* src = reinterpret_cast<const float4*>(
            input + (size_t)(row0 + r) * DIM + p * 64);
        #pragma unroll
        for (int u = 0; u < 8; ++u) {
            float4 fa = src[u * 2 + 0];
            float4 fb = src[u * 2 + 1];
            __half2 h0 = __floats2half2_rn(fa.x, fa.y);
            __half2 h1 = __floats2half2_rn(fa.z, fa.w);
            __half2 h2 = __floats2half2_rn(fb.x, fb.y);
            __half2 h3 = __floats2half2_rn(fb.z, fb.w);
            uint4 pk;
            pk.x = *reinterpret_cast<uint32_t*>(&h0);
            pk.y = *reinterpret_cast<uint32_t*>(&h1);
            pk.z = *reinterpret_cast<uint32_t*>(&h2);
            pk.w = *reinterpret_cast<uint32_t*>(&h3);
            int g = p * 8 + u;
            int swg = (g & 24) | ((g ^ r) & 7);
            *reinterpret_cast<uint4*>(
                reinterpret_cast<char*>(stage) + r * 512 + swg * 16) = pk;
        }
        __syncthreads();
        #pragma unroll
        for (int mt = 0; mt < 2; ++mt) {
            const int m = mt * 16 + (mat & 1) * 8 + rr;
            #pragma unroll
            for (int c = 0; c < 16; ++c) {
                int g = c * 2 + (mat >> 1);
                int swg = (g & 24) | ((g ^ rr) & 7);
                uint32_t addr = smem_u32(stage) + (uint32_t)(m * 512 + swg * 16);
                ldmx4(areg[mt * 64 + c * 4 + 0], areg[mt * 64 + c * 4 + 1],
                      areg[mt * 64 + c * 4 + 2], areg[mt * 64 + c * 4 + 3], addr);
            }
        }
    }

    // ================= main loop: LDG-direct B, 4 accumulator chains =======
    const uint4* bp = reinterpret_cast<const uint4*>(g_epk);
    const int q = half * 4 + wid;    // global 1024-code quarter

    float bb[4] = {-3.0e38f, -3.0e38f, -3.0e38f, -3.0e38f};
    float ss[4] = {-3.0e38f, -3.0e38f, -3.0e38f, -3.0e38f};
    int   ii[4] = {0, 0, 0, 0};

    uint4 br[4];   // 4-slot ring, prefetch distance 4 g-steps
    {
        int id0 = q * 128;
        int b0 = ((id0 >> 3) * 64 + (id0 & 7)) * 32 + lane;
        #pragma unroll
        for (int g = 0; g < 4; ++g) br[g] = bp[b0 + g * 256];
    }

    #pragma unroll 1
    for (int u = 0; u < 128; ++u) {
        const int id    = q * 128 + u;
        const int base  = ((id >> 3) * 64 + (id & 7)) * 32 + lane;
        const int idn   = id + 1;
        const int basen = (u < 127) ? ((idn >> 3) * 64 + (idn & 7)) * 32 + lane : base;

        // norms folded into chain-A init (R14-verified numerics)
        float2 c2 = __ldg(reinterpret_cast<const float2*>(g_c) + id * 4 + (lane & 3));

        float creg[16];
        creg[0] = -c2.x; creg[1] = -c2.y; creg[2] = -c2.x; creg[3] = -c2.y;
        creg[4] = 0.f;   creg[5] = 0.f;   creg[6] = 0.f;   creg[7] = 0.f;
        creg[8] = -c2.x; creg[9] = -c2.y; creg[10] = -c2.x; creg[11] = -c2.y;
        creg[12] = 0.f;  creg[13] = 0.f;  creg[14] = 0.f;  creg[15] = 0.f;

        #pragma unroll
        for (int g = 0; g < 8; ++g) {
            const uint4 b = br[g & 3];
            const int paddr = (g < 4) ? (base + (g + 4) * 256)
                                      : (basen + (g - 4) * 256);
            br[g & 3] = bp[paddr];
            mma16816(creg + 0,  areg + (2 * g) * 4,          b.x, b.y);  // m0 chain A
            mma16816(creg + 4,  areg + (2 * g + 1) * 4,      b.z, b.w);  // m0 chain B
            mma16816(creg + 8,  areg + 64 + (2 * g) * 4,     b.x, b.y);  // m1 chain A
            mma16816(creg + 12, areg + 64 + (2 * g + 1) * 4, b.z, b.w);  // m1 chain B
        }

        // merge chains (norm already folded) + running top-2 (4 slots)
        int n0 = id * 8 + (lane & 3) * 2;
        float v;
        v = creg[0] + creg[4];
        if (v > bb[0]) { ss[0] = bb[0]; bb[0] = v; ii[0] = n0; } else if (v > ss[0]) ss[0] = v;
        v = creg[1] + creg[5];
        if (v > bb[0]) { ss[0] = bb[0]; bb[0] = v; ii[0] = n0 + 1; } else if (v > ss[0]) ss[0] = v;
        v = creg[2] + creg[6];
        if (v > bb[1]) { ss[1] = bb[1]; bb[1] = v; ii[1] = n0; } else if (v > ss[1]) ss[1] = v;
        v = creg[3] + creg[7];
        if (v > bb[1]) { ss[1] = bb[1]; bb[1] = v; ii[1] = n0 + 1; } else if (v > ss[1]) ss[1] = v;
        v = creg[8] + creg[12];
        if (v > bb[2]) { ss[2] = bb[2]; bb[2] = v; ii[2] = n0; } else if (v > ss[2]) ss[2] = v;
        v = creg[9] + creg[13];
        if (v > bb[2]) { ss[2] = bb[2]; bb[2] = v; ii[2] = n0 + 1; } else if (v > ss[2]) ss[2] = v;
        v = creg[10] + creg[14];
        if (v > bb[3]) { ss[3] = bb[3]; bb[3] = v; ii[3] = n0; } else if (v > ss[3]) ss[3] = v;
        v = creg[11] + creg[15];
        if (v > bb[3]) { ss[3] = bb[3]; bb[3] = v; ii[3] = n0 + 1; } else if (v > ss[3]) ss[3] = v;
    }

    // ================= reduction =================
    #pragma unroll
    for (int sl = 0; sl < 4; ++sl) {
        float b2 = bb[sl], sec = ss[sl]; int i = ii[sl];
        #pragma unroll
        for (int off = 1; off <= 2; off <<= 1) {
            float ob = __shfl_xor_sync(0xffffffffu, b2, off);
            float os = __shfl_xor_sync(0xffffffffu, sec, off);
            int   oi = __shfl_xor_sync(0xffffffffu, i, off);
            if (ob > b2 || (ob == b2 && oi < i)) {
                sec = fmaxf(b2, os); b2 = ob; i = oi;
            } else {
                sec = fmaxf(sec, ob);
            }
        }
        if ((lane & 3) == 0) {
            int lrow = (sl >> 1) * 16 + (sl & 1) * 8 + (lane >> 2);
            sbv[wid][lrow] = b2;
            ssv[wid][lrow] = sec;
            sbi[wid][lrow] = i;
        }
    }
    __syncthreads();

    // merge 4 warps (disjoint quarters) per row -> per-half scratch
    if (tid < 32) {
        float va = sbv[0][tid], sa = ssv[0][tid];
        int   ia = sbi[0][tid];
        #pragma unroll
        for (int w = 1; w < 4; ++w) {
            float vb = sbv[w][tid], sb = ssv[w][tid];
            int   ib = sbi[w][tid];
            if (vb > va || (vb == va && ib < ia)) {
                sa = fmaxf(va, sb); va = vb; ia = ib;
            } else {
                sa = fmaxf(sa, vb);
            }
        }
        int row = row0 + tid;
        g_hb[half][row] = va;
        g_hs[half][row] = sa;
        g_hi[half][row] = ia;
    }
}

// ============================================================
// Merge the two code-halves per row; write index; flag narrow margins.
// ============================================================
__global__ void merge_kernel() {
    int row = blockIdx.x * 256 + threadIdx.x;
    float b0 = g_hb[0][row], b1 = g_hb[1][row];
    float s0 = g_hs[0][row], s1 = g_hs[1][row];
    int   i0 = g_hi[0][row], i1 = g_hi[1][row];
    float bv, sec; int bi;
    if (b1 > b0) { bv = b1; bi = i1; sec = fmaxf(b0, s1); }   // tie -> half0 (lower idx)
    else         { bv = b0; bi = i0; sec = fmaxf(b1, s0); }
    g_idx[row] = bi;
    if (bv - sec < THRESH) {
        int s = atomicAdd(&g_nflag, 1);
        if (s < FLAG_CAP) { g_flag[s] = row; g_rkey[s] = 0ull; }
    }
}

// ============================================================
// Exact fp32 rescue for narrow-margin rows.
// ============================================================
__device__ __forceinline__ unsigned long long score_key(float v, int j) {
    uint32_t u = __float_as_uint(v);
    u = (u & 0x80000000u) ? ~u : (u | 0x80000000u);
    return ((unsigned long long)u << 32) | (uint32_t)(0xFFFFFFFFu ^ (uint32_t)j);
}

__global__ void rescue_kernel(const float* __restrict__ input,
                              const float* __restrict__ embed) {
    __shared__ float xs[16][DIM];
    __shared__ unsigned long long wb[8][16];
    int nf = g_nflag; if (nf > FLAG_CAP) nf = FLAG_CAP;
    const int tid = threadIdx.x, wid = tid >> 5, lane = tid & 31;

    for (int base = blockIdx.y * 16; base < nf; base += 16 * 16) {
        int nrows = nf - base; if (nrows > 16) nrows = 16;
        __syncthreads();
        for (int i = tid; i < nrows * DIM; i += 256) {
            int r = i >> 8, d = i & 255;
            xs[r][d] = input[(size_t)g_flag[base + r] * DIM + d];
        }
        __syncthreads();

        int j0 = blockIdx.x * 1024 + tid;     // codes j0 + {0,256,512,768}
        float acc[4][16];
        #pragma unroll
        for (int qq = 0; qq < 4; ++qq)
            #pragma unroll
            for (int r = 0; r < 16; ++r) acc[qq][r] = 0.f;

        #pragma unroll 4
        for (int d = 0; d < DIM; ++d) {
            float e0 = embed[(size_t)d * NE + j0];
            float e1 = embed[(size_t)d * NE + j0 + 256];
            float e2 = embed[(size_t)d * NE + j0 + 512];
            float e3 = embed[(size_t)d * NE + j0 + 768];
            #pragma unroll
            for (int r = 0; r < 16; ++r) {
                float x = xs[r][d];
                acc[0][r] += e0 * x;
                acc[1][r] += e1 * x;
                acc[2][r] += e2 * x;
                acc[3][r] += e3 * x;
            }
        }
        float c0 = g_c[j0], c1 = g_c[j0 + 256], c2 = g_c[j0 + 512], c3 = g_c[j0 + 768];

        #pragma unroll 1
        for (int r = 0; r < 16; ++r) {
            float bv = acc[0][r] - c0; int bj = j0;
            float v1 = acc[1][r] - c1; if (v1 > bv) { bv = v1; bj = j0 + 256; }
            float v2 = acc[2][r] - c2; if (v2 > bv) { bv = v2; bj = j0 + 512; }
            float v3 = acc[3][r] - c3; if (v3 > bv) { bv = v3; bj = j0 + 768; }
            unsigned long long key = score_key(bv, bj);
            #pragma unroll
            for (int o = 16; o; o >>= 1) {
                unsigned long long other = __shfl_xor_sync(0xffffffffu, key, o);
                if (other > key) key = other;
            }
            if (lane == 0) wb[wid][r] = key;
        }
        __syncthreads();
        if (tid < nrows) {
            unsigned long long k = wb[0][tid];
            #pragma unroll
            for (int w = 1; w < 8; ++w) if (wb[w][tid] > k) k = wb[w][tid];
            atomicMax(&g_rkey[base + tid], k);
        }
    }
}

__global__ void extract_kernel() {
    int nf = g_nflag; if (nf > FLAG_CAP) nf = FLAG_CAP;
    for (int i = threadIdx.x; i < nf; i += 256) {
        unsigned long long k = g_rkey[i];
        g_idx[g_flag[i]] = (int)(0xFFFFFFFFu ^ (uint32_t)(k & 0xFFFFFFFFull));
    }
}

// ============================================================
// Output: gather, commitment loss, indices. 4 rows per warp (MLP on idx).
// ============================================================
__global__ void output_kernel(const float* __restrict__ input,
                              float* __restrict__ out, int write_extra) {
    int wid  = threadIdx.x >> 5;
    int lane = threadIdx.x & 31;
    int r0 = (blockIdx.x * 8 + wid) * 4;

    int j[4];
    #pragma unroll
    for (int k = 0; k < 4; ++k) j[k] = g_idx[r0 + k];

    float s = 0.f;
    #pragma unroll
    for (int k = 0; k < 4; ++k) {
        const float4* x4 = reinterpret_cast<const float4*>(input + (size_t)(r0 + k) * DIM);
        const float4* e4 = reinterpret_cast<const float4*>(g_eT + (size_t)j[k] * DIM);
        float4*       q4 = reinterpret_cast<float4*>(out + (size_t)(r0 + k) * DIM);
        #pragma unroll
        for (int t = 0; t < 2; ++t) {
            int d4 = lane + t * 32;
            float4 e = e4[d4];
            float4 x = x4[d4];
            q4[d4] = e;
            float a = e.x - x.x, b = e.y - x.y, c = e.z - x.z, d = e.w - x.w;
            s += a * a + b * b + c * c + d * d;
        }
    }
    #pragma unroll
    for (int o = 16; o; o >>= 1) s += __shfl_xor_sync(0xffffffffu, s, o);
    if (lane == 0) {
        atomicAdd(&g_diff, (double)s);
        if (write_extra) {
            #pragma unroll
            for (int k = 0; k < 4; ++k)
                out[(size_t)NROWS * DIM + 1 + r0 + k] = (float)j[k];
        }
    }
}

__global__ void finalize_kernel(float* __restrict__ out, int write_extra) {
    if (write_extra)
        out[(size_t)NROWS * DIM] = (float)(g_diff * (1.0 / ((double)NROWS * (double)DIM)));
}

// ============================================================
extern "C" void kernel_launch(void* const* d_in, const int* in_sizes, int n_in,
                              void* d_out, int out_size) {
    const float* input = (const float*)d_in[0];
    const float* embed = (const float*)d_in[1];
    if (in_sizes[0] == NE * DIM && in_sizes[1] == NROWS * DIM) {
        input = (const float*)d_in[1];
        embed = (const float*)d_in[0];
    }
    float* out = (float*)d_out;
    int write_extra = (out_size >= NROWS * DIM + 1 + NROWS) ? 1 : 0;

    norms_part_kernel<<<dim3(NE / 256, 4), 256>>>(embed);
    norms_comb_kernel<<<NE / 256, 256>>>();
    transpose_pack_kernel<<<dim3(NE / 32, DIM / 32), dim3(32, 8)>>>(embed);
    tc_argmin_kernel<<<NROWS / 32 * 2, 128>>>(input);
    merge_kernel<<<NROWS / 256, 256>>>();
    rescue_kernel<<<dim3(8, 16), 256>>>(input, embed);
    extract_kernel<<<1, 256>>>();
    output_kernel<<<NROWS / 32, 256>>>(input, out, write_extra);
    finalize_kernel<<<1, 1>>>(out, write_extra);
}

// round 16
// speedup vs baseline: 1.3657x; 1.3657x over previous
#include <cuda_runtime.h>
#include <cuda_fp16.h>
#include <cstdint>

#define DIM    256
#define NE     8192
#define NROWS  32768
#define THRESH 0.04f
#define FLAG_CAP NROWS

// ---- device scratch ----
__device__ float  g_c[NE];                 // 0.5*||e_j||^2
__device__ float  g_cp[4][NE];             // norm partials (deterministic combine)
__device__ int    g_idx[NROWS];
__device__ float  g_eT[NE * DIM];          // fp32 transposed codebook (gather)
__device__ __half g_epk[NE * DIM];         // fp16 codebook, pre-packed MMA B-fragments
__device__ double g_diff;
__device__ int    g_nflag;
__device__ int    g_flag[FLAG_CAP];
__device__ unsigned long long g_rkey[FLAG_CAP];

__device__ __forceinline__ uint32_t smem_u32(const void* p) {
    uint32_t a;
    asm("{ .reg .u64 t; cvta.to.shared.u64 t, %1; cvt.u32.u64 %0, t; }" : "=r"(a) : "l"(p));
    return a;
}

__device__ __forceinline__ void ldmx4(uint32_t& r0, uint32_t& r1, uint32_t& r2, uint32_t& r3,
                                      uint32_t addr) {
    asm volatile("ldmatrix.sync.aligned.m8n8.x4.shared.b16 {%0,%1,%2,%3}, [%4];"
                 : "=r"(r0), "=r"(r1), "=r"(r2), "=r"(r3) : "r"(addr));
}

__device__ __forceinline__ void mma16816(float* c,
                                         const uint32_t* a,
                                         uint32_t b0, uint32_t b1) {
    asm volatile(
        "mma.sync.aligned.m16n8k16.row.col.f32.f16.f16.f32 "
        "{%0,%1,%2,%3}, {%4,%5,%6,%7}, {%8,%9}, {%0,%1,%2,%3};"
        : "+f"(c[0]), "+f"(c[1]), "+f"(c[2]), "+f"(c[3])
        : "r"(a[0]), "r"(a[1]), "r"(a[2]), "r"(a[3]), "r"(b0), "r"(b1));
}

// ============================================================
// Prep kernels
// ============================================================
__global__ void norms_part_kernel(const float* __restrict__ embed) {
    int j = blockIdx.x * 256 + threadIdx.x;
    int q = blockIdx.y;                    // dim quarter
    float s = 0.f;
    #pragma unroll 8
    for (int d = q * 64; d < q * 64 + 64; ++d) {
        float v = embed[(size_t)d * NE + j];
        s += v * v;
    }
    g_cp[q][j] = s;
}

__global__ void norms_comb_kernel() {
    int j = blockIdx.x * 256 + threadIdx.x;
    if (blockIdx.x == 0 && threadIdx.x == 0) { g_diff = 0.0; g_nflag = 0; }
    g_c[j] = 0.5f * (((g_cp[0][j] + g_cp[1][j]) + g_cp[2][j]) + g_cp[3][j]);
}

// Fused transpose (-> g_eT) + fp16 fragment pack (-> g_epk).
// Fragment unit (jt, ncol, g, p) = 512B: n8 x k32 (32 lanes x 16B).
// Lane l = nl*4 + ((kk>>1)&3), halves h = (kk>>3)*2 + (kk&1).
__global__ void transpose_pack_kernel(const float* __restrict__ embed) {
    __shared__ float t[32][33];
    int j0 = blockIdx.x * 32;
    int d0 = blockIdx.y * 32;
    int tx = threadIdx.x, ty = threadIdx.y;   // 32 x 8
    #pragma unroll
    for (int i = 0; i < 32; i += 8) {
        int d = d0 + ty + i;
        int j = j0 + tx;
        float v = embed[(size_t)d * NE + j];
        t[ty + i][tx] = v;
        // pack fragment element
        int jt = j >> 7;
        int ncol = (j >> 6) & 1;
        int p = (j >> 3) & 7;
        int nl = j & 7;
        int g = d >> 5;
        int kk = d & 31;
        int l = nl * 4 + ((kk >> 1) & 3);
        int h = ((kk >> 3) << 1) + (kk & 1);
        size_t unit = ((size_t)(jt * 2 + ncol) * 8 + g) * 8 + p;
        g_epk[unit * 256 + l * 8 + h] = __float2half(v);
    }
    __syncthreads();
    #pragma unroll
    for (int i = 0; i < 32; i += 8)
        g_eT[(size_t)(j0 + ty + i) * DIM + (d0 + tx)] = t[tx][ty + i];
}

// ============================================================
// Main HMMA kernel (R12 structure): 128 threads (4 warps), 32 rows/CTA,
// 1024 CTAs. Warp: m32 x distinct 2048-code quarter; B LDG-direct,
// 4-slot ring. Norms folded into chain-A accumulator init.
// ============================================================
__global__ void __launch_bounds__(128, 2)
tc_argmin_kernel(const float* __restrict__ input) {
    __shared__ __align__(16) __half stage[8192];  // 16KB: 32-row A staging
    __shared__ float sbv[4][32];
    __shared__ float ssv[4][32];
    __shared__ int   sbi[4][32];

    const int tid  = threadIdx.x;
    const int wid  = tid >> 5;    // warp = code quarter
    const int lane = tid & 31;
    const int row0 = blockIdx.x * 32;
    const int mat  = lane >> 3;
    const int rr   = lane & 7;

    // ================= prologue: A fragments (both m16 tiles) ==============
    uint32_t areg[128];   // 2 m-tiles x 16 k16-chunks x 4
    {
        const int r = tid & 31;     // row
        const int p = tid >> 5;     // segment 0..3 (64 halves each)
        const float4* src = reinterpret_cast<const float4*>(
            input + (size_t)(row0 + r) * DIM + p * 64);
        #pragma unroll
        for (int u = 0; u < 8; ++u) {
            float4 fa = src[u * 2 + 0];
            float4 fb = src[u * 2 + 1];
            __half2 h0 = __floats2half2_rn(fa.x, fa.y);
            __half2 h1 = __floats2half2_rn(fa.z, fa.w);
            __half2 h2 = __floats2half2_rn(fb.x, fb.y);
            __half2 h3 = __floats2half2_rn(fb.z, fb.w);
            uint4 pk;
            pk.x = *reinterpret_cast<uint32_t*>(&h0);
            pk.y = *reinterpret_cast<uint32_t*>(&h1);
            pk.z = *reinterpret_cast<uint32_t*>(&h2);
            pk.w = *reinterpret_cast<uint32_t*>(&h3);
            int g = p * 8 + u;
            int swg = (g & 24) | ((g ^ r) & 7);
            *reinterpret_cast<uint4*>(
                reinterpret_cast<char*>(stage) + r * 512 + swg * 16) = pk;
        }
        __syncthreads();
        #pragma unroll
        for (int mt = 0; mt < 2; ++mt) {
            const int m = mt * 16 + (mat & 1) * 8 + rr;
            #pragma unroll
            for (int c = 0; c < 16; ++c) {
                int g = c * 2 + (mat >> 1);
                int swg = (g & 24) | ((g ^ rr) & 7);
                uint32_t addr = smem_u32(stage) + (uint32_t)(m * 512 + swg * 16);
                ldmx4(areg[mt * 64 + c * 4 + 0], areg[mt * 64 + c * 4 + 1],
                      areg[mt * 64 + c * 4 + 2], areg[mt * 64 + c * 4 + 3], addr);
            }
        }
    }

    // ================= main loop: LDG-direct B, 4 accumulator chains =======
    const uint4* bp = reinterpret_cast<const uint4*>(g_epk);
    const int q = wid;

    float bb[4] = {-3.0e38f, -3.0e38f, -3.0e38f, -3.0e38f};
    float ss[4] = {-3.0e38f, -3.0e38f, -3.0e38f, -3.0e38f};
    int   ii[4] = {0, 0, 0, 0};

    uint4 br[4];   // 4-slot ring, prefetch distance 4 g-steps
    {
        int id0 = q * 256;
        int b0 = ((id0 >> 3) * 64 + (id0 & 7)) * 32 + lane;
        #pragma unroll
        for (int g = 0; g < 4; ++g) br[g] = bp[b0 + g * 256];
    }

    #pragma unroll 1
    for (int u = 0; u < 256; ++u) {
        const int id    = q * 256 + u;
        const int base  = ((id >> 3) * 64 + (id & 7)) * 32 + lane;
        const int idn   = id + 1;
        const int basen = (u < 255) ? ((idn >> 3) * 64 + (idn & 7)) * 32 + lane : base;

        // norms folded into chain-A init (verified: rel_err unchanged)
        float2 c2 = __ldg(reinterpret_cast<const float2*>(g_c) + id * 4 + (lane & 3));

        float creg[16];
        creg[0] = -c2.x; creg[1] = -c2.y; creg[2] = -c2.x; creg[3] = -c2.y;
        creg[4] = 0.f;   creg[5] = 0.f;   creg[6] = 0.f;   creg[7] = 0.f;
        creg[8] = -c2.x; creg[9] = -c2.y; creg[10] = -c2.x; creg[11] = -c2.y;
        creg[12] = 0.f;  creg[13] = 0.f;  creg[14] = 0.f;  creg[15] = 0.f;

        #pragma unroll
        for (int g = 0; g < 8; ++g) {
            const uint4 b = br[g & 3];
            const int paddr = (g < 4) ? (base + (g + 4) * 256)
                                      : (basen + (g - 4) * 256);
            br[g & 3] = bp[paddr];
            mma16816(creg + 0,  areg + (2 * g) * 4,          b.x, b.y);  // m0 chain A
            mma16816(creg + 4,  areg + (2 * g + 1) * 4,      b.z, b.w);  // m0 chain B
            mma16816(creg + 8,  areg + 64 + (2 * g) * 4,     b.x, b.y);  // m1 chain A
            mma16816(creg + 12, areg + 64 + (2 * g + 1) * 4, b.z, b.w);  // m1 chain B
        }

        // merge chains (norm folded) + running top-2 (4 slots)
        int n0 = id * 8 + (lane & 3) * 2;
        float v;
        v = creg[0] + creg[4];
        if (v > bb[0]) { ss[0] = bb[0]; bb[0] = v; ii[0] = n0; } else if (v > ss[0]) ss[0] = v;
        v = creg[1] + creg[5];
        if (v > bb[0]) { ss[0] = bb[0]; bb[0] = v; ii[0] = n0 + 1; } else if (v > ss[0]) ss[0] = v;
        v = creg[2] + creg[6];
        if (v > bb[1]) { ss[1] = bb[1]; bb[1] = v; ii[1] = n0; } else if (v > ss[1]) ss[1] = v;
        v = creg[3] + creg[7];
        if (v > bb[1]) { ss[1] = bb[1]; bb[1] = v; ii[1] = n0 + 1; } else if (v > ss[1]) ss[1] = v;
        v = creg[8] + creg[12];
        if (v > bb[2]) { ss[2] = bb[2]; bb[2] = v; ii[2] = n0; } else if (v > ss[2]) ss[2] = v;
        v = creg[9] + creg[13];
        if (v > bb[2]) { ss[2] = bb[2]; bb[2] = v; ii[2] = n0 + 1; } else if (v > ss[2]) ss[2] = v;
        v = creg[10] + creg[14];
        if (v > bb[3]) { ss[3] = bb[3]; bb[3] = v; ii[3] = n0; } else if (v > ss[3]) ss[3] = v;
        v = creg[11] + creg[15];
        if (v > bb[3]) { ss[3] = bb[3]; bb[3] = v; ii[3] = n0 + 1; } else if (v > ss[3]) ss[3] = v;
    }

    // ================= reduction =================
    // quad merge within warp (lanes 0..3 of each quad hold different codes)
    #pragma unroll
    for (int sl = 0; sl < 4; ++sl) {
        float b2 = bb[sl], sec = ss[sl]; int i = ii[sl];
        #pragma unroll
        for (int off = 1; off <= 2; off <<= 1) {
            float ob = __shfl_xor_sync(0xffffffffu, b2, off);
            float os = __shfl_xor_sync(0xffffffffu, sec, off);
            int   oi = __shfl_xor_sync(0xffffffffu, i, off);
            if (ob > b2 || (ob == b2 && oi < i)) {
                sec = fmaxf(b2, os); b2 = ob; i = oi;
            } else {
                sec = fmaxf(sec, ob);
            }
        }
        if ((lane & 3) == 0) {
            int lrow = (sl >> 1) * 16 + (sl & 1) * 8 + (lane >> 2);
            sbv[wid][lrow] = b2;
            ssv[wid][lrow] = sec;
            sbi[wid][lrow] = i;
        }
    }
    __syncthreads();

    // merge 4 warps (disjoint code quarters) per row; write + flag
    if (tid < 32) {
        float va = sbv[0][tid], sa = ssv[0][tid];
        int   ia = sbi[0][tid];
        #pragma unroll
        for (int w = 1; w < 4; ++w) {
            float vb = sbv[w][tid], sb = ssv[w][tid];
            int   ib = sbi[w][tid];
            if (vb > va || (vb == va && ib < ia)) {
                sa = fmaxf(va, sb); va = vb; ia = ib;
            } else {
                sa = fmaxf(sa, vb);
            }
        }
        int row = row0 + tid;
        g_idx[row] = ia;
        if (va - sa < THRESH) {
            int sidx = atomicAdd(&g_nflag, 1);
            if (sidx < FLAG_CAP) { g_flag[sidx] = row; g_rkey[sidx] = 0ull; }
        }
    }
}

// ============================================================
// Exact fp32 rescue for narrow-margin rows.
// ============================================================
__device__ __forceinline__ unsigned long long score_key(float v, int j) {
    uint32_t u = __float_as_uint(v);
    u = (u & 0x80000000u) ? ~u : (u | 0x80000000u);
    return ((unsigned long long)u << 32) | (uint32_t)(0xFFFFFFFFu ^ (uint32_t)j);
}

__global__ void rescue_kernel(const float* __restrict__ input,
                              const float* __restrict__ embed) {
    __shared__ float xs[16][DIM];
    __shared__ unsigned long long wb[8][16];
    int nf = g_nflag; if (nf > FLAG_CAP) nf = FLAG_CAP;
    const int tid = threadIdx.x, wid = tid >> 5, lane = tid & 31;

    for (int base = blockIdx.y * 16; base < nf; base += 16 * 16) {
        int nrows = nf - base; if (nrows > 16) nrows = 16;
        __syncthreads();
        for (int i = tid; i < nrows * DIM; i += 256) {
            int r = i >> 8, d = i & 255;
            xs[r][d] = input[(size_t)g_flag[base + r] * DIM + d];
        }
        __syncthreads();

        int j0 = blockIdx.x * 1024 + tid;     // codes j0 + {0,256,512,768}
        float acc[4][16];
        #pragma unroll
        for (int qq = 0; qq < 4; ++qq)
            #pragma unroll
            for (int r = 0; r < 16; ++r) acc[qq][r] = 0.f;

        #pragma unroll 4
        for (int d = 0; d < DIM; ++d) {
            float e0 = embed[(size_t)d * NE + j0];
            float e1 = embed[(size_t)d * NE + j0 + 256];
            float e2 = embed[(size_t)d * NE + j0 + 512];
            float e3 = embed[(size_t)d * NE + j0 + 768];
            #pragma unroll
            for (int r = 0; r < 16; ++r) {
                float x = xs[r][d];
                acc[0][r] += e0 * x;
                acc[1][r] += e1 * x;
                acc[2][r] += e2 * x;
                acc[3][r] += e3 * x;
            }
        }
        float c0 = g_c[j0], c1 = g_c[j0 + 256], c2 = g_c[j0 + 512], c3 = g_c[j0 + 768];

        #pragma unroll 1
        for (int r = 0; r < 16; ++r) {
            float bv = acc[0][r] - c0; int bj = j0;
            float v1 = acc[1][r] - c1; if (v1 > bv) { bv = v1; bj = j0 + 256; }
            float v2 = acc[2][r] - c2; if (v2 > bv) { bv = v2; bj = j0 + 512; }
            float v3 = acc[3][r] - c3; if (v3 > bv) { bv = v3; bj = j0 + 768; }
            unsigned long long key = score_key(bv, bj);
            #pragma unroll
            for (int o = 16; o; o >>= 1) {
                unsigned long long other = __shfl_xor_sync(0xffffffffu, key, o);
                if (other > key) key = other;
            }
            if (lane == 0) wb[wid][r] = key;
        }
        __syncthreads();
        if (tid < nrows) {
            unsigned long long k = wb[0][tid];
            #pragma unroll
            for (int w = 1; w < 8; ++w) if (wb[w][tid] > k) k = wb[w][tid];
            atomicMax(&g_rkey[base + tid], k);
        }
    }
}

__global__ void extract_kernel() {
    int nf = g_nflag; if (nf > FLAG_CAP) nf = FLAG_CAP;
    for (int i = threadIdx.x; i < nf; i += 256) {
        unsigned long long k = g_rkey[i];
        g_idx[g_flag[i]] = (int)(0xFFFFFFFFu ^ (uint32_t)(k & 0xFFFFFFFFull));
    }
}

// ============================================================
// Output: gather, commitment loss, indices. 4 rows per warp (MLP on idx).
// ============================================================
__global__ void output_kernel(const float* __restrict__ input,
                              float* __restrict__ out, int write_extra) {
    int wid  = threadIdx.x >> 5;
    int lane = threadIdx.x & 31;
    int r0 = (blockIdx.x * 8 + wid) * 4;

    int j[4];
    #pragma unroll
    for (int k = 0; k < 4; ++k) j[k] = g_idx[r0 + k];

    float s = 0.f;
    #pragma unroll
    for (int k = 0; k < 4; ++k) {
        const float4* x4 = reinterpret_cast<const float4*>(input + (size_t)(r0 + k) * DIM);
        const float4* e4 = reinterpret_cast<const float4*>(g_eT + (size_t)j[k] * DIM);
        float4*       q4 = reinterpret_cast<float4*>(out + (size_t)(r0 + k) * DIM);
        #pragma unroll
        for (int t = 0; t < 2; ++t) {
            int d4 = lane + t * 32;
            float4 e = e4[d4];
            float4 x = x4[d4];
            q4[d4] = e;
            float a = e.x - x.x, b = e.y - x.y, c = e.z - x.z, d = e.w - x.w;
            s += a * a + b * b + c * c + d * d;
        }
    }
    #pragma unroll
    for (int o = 16; o; o >>= 1) s += __shfl_xor_sync(0xffffffffu, s, o);
    if (lane == 0) {
        atomicAdd(&g_diff, (double)s);
        if (write_extra) {
            #pragma unroll
            for (int k = 0; k < 4; ++k)
                out[(size_t)NROWS * DIM + 1 + r0 + k] = (float)j[k];
        }
    }
}

__global__ void finalize_kernel(float* __restrict__ out, int write_extra) {
    if (write_extra)
        out[(size_t)NROWS * DIM] = (float)(g_diff * (1.0 / ((double)NROWS * (double)DIM)));
}

// ============================================================
extern "C" void kernel_launch(void* const* d_in, const int* in_sizes, int n_in,
                              void* d_out, int out_size) {
    const float* input = (const float*)d_in[0];
    const float* embed = (const float*)d_in[1];
    if (in_sizes[0] == NE * DIM && in_sizes[1] == NROWS * DIM) {
        input = (const float*)d_in[1];
        embed = (const float*)d_in[0];
    }
    float* out = (float*)d_out;
    int write_extra = (out_size >= NROWS * DIM + 1 + NROWS) ? 1 : 0;

    norms_part_kernel<<<dim3(NE / 256, 4), 256>>>(embed);
    norms_comb_kernel<<<NE / 256, 256>>>();
    transpose_pack_kernel<<<dim3(NE / 32, DIM / 32), dim3(32, 8)>>>(embed);
    tc_argmin_kernel<<<NROWS / 32, 128>>>(input);
    rescue_kernel<<<dim3(8, 16), 256>>>(input, embed);
    extract_kernel<<<1, 256>>>();
    output_kernel<<<NROWS / 32, 256>>>(input, out, write_extra);
    finalize_kernel<<<1, 1>>>(out, write_extra);
}

// round 17
// speedup vs baseline: 1.4898x; 1.0908x over previous
#include <cuda_runtime.h>
#include <cuda_fp16.h>
#include <cstdint>

#define DIM    256
#define NE     8192
#define NROWS  32768
#define THRESH 0.04f
#define FLAG_CAP NROWS

// ---- device scratch ----
__device__ float  g_c[NE];                 // 0.5*||e_j||^2
__device__ float  g_cp[4][NE];             // norm partials (deterministic combine)
__device__ int    g_idx[NROWS];
__device__ float  g_eT[NE * DIM];          // fp32 transposed codebook (gather)
__device__ __half g_epk[NE * DIM];         // fp16 codebook, pre-packed MMA B-fragments
__device__ double g_diff;
__device__ int    g_nflag;
__device__ int    g_flag[FLAG_CAP];
__device__ unsigned long long g_rkey[FLAG_CAP];

__device__ __forceinline__ uint32_t smem_u32(const void* p) {
    uint32_t a;
    asm("{ .reg .u64 t; cvta.to.shared.u64 t, %1; cvt.u32.u64 %0, t; }" : "=r"(a) : "l"(p));
    return a;
}

__device__ __forceinline__ void ldmx4(uint32_t& r0, uint32_t& r1, uint32_t& r2, uint32_t& r3,
                                      uint32_t addr) {
    asm volatile("ldmatrix.sync.aligned.m8n8.x4.shared.b16 {%0,%1,%2,%3}, [%4];"
                 : "=r"(r0), "=r"(r1), "=r"(r2), "=r"(r3) : "r"(addr));
}

__device__ __forceinline__ void mma16816(float* c,
                                         const uint32_t* a,
                                         uint32_t b0, uint32_t b1) {
    asm volatile(
        "mma.sync.aligned.m16n8k16.row.col.f32.f16.f16.f32 "
        "{%0,%1,%2,%3}, {%4,%5,%6,%7}, {%8,%9}, {%0,%1,%2,%3};"
        : "+f"(c[0]), "+f"(c[1]), "+f"(c[2]), "+f"(c[3])
        : "r"(a[0]), "r"(a[1]), "r"(a[2]), "r"(a[3]), "r"(b0), "r"(b1));
}

// ============================================================
// Prep kernels
// ============================================================
__global__ void norms_part_kernel(const float* __restrict__ embed) {
    int j = blockIdx.x * 256 + threadIdx.x;
    int q = blockIdx.y;                    // dim quarter
    float s = 0.f;
    #pragma unroll 8
    for (int d = q * 64; d < q * 64 + 64; ++d) {
        float v = embed[(size_t)d * NE + j];
        s += v * v;
    }
    g_cp[q][j] = s;
}

__global__ void norms_comb_kernel() {
    int j = blockIdx.x * 256 + threadIdx.x;
    if (blockIdx.x == 0 && threadIdx.x == 0) { g_diff = 0.0; g_nflag = 0; }
    g_c[j] = 0.5f * (((g_cp[0][j] + g_cp[1][j]) + g_cp[2][j]) + g_cp[3][j]);
}

// Fused transpose (-> g_eT) + fp16 fragment pack (-> g_epk).
// Fragment unit (jt, ncol, g, p) = 512B: n8 x k32 (32 lanes x 16B).
// Lane l = nl*4 + ((kk>>1)&3), halves h = (kk>>3)*2 + (kk&1).
__global__ void transpose_pack_kernel(const float* __restrict__ embed) {
    __shared__ float t[32][33];
    int j0 = blockIdx.x * 32;
    int d0 = blockIdx.y * 32;
    int tx = threadIdx.x, ty = threadIdx.y;   // 32 x 8
    #pragma unroll
    for (int i = 0; i < 32; i += 8) {
        int d = d0 + ty + i;
        int j = j0 + tx;
        float v = embed[(size_t)d * NE + j];
        t[ty + i][tx] = v;
        // pack fragment element
        int jt = j >> 7;
        int ncol = (j >> 6) & 1;
        int p = (j >> 3) & 7;
        int nl = j & 7;
        int g = d >> 5;
        int kk = d & 31;
        int l = nl * 4 + ((kk >> 1) & 3);
        int h = ((kk >> 3) << 1) + (kk & 1);
        size_t unit = ((size_t)(jt * 2 + ncol) * 8 + g) * 8 + p;
        g_epk[unit * 256 + l * 8 + h] = __float2half(v);
    }
    __syncthreads();
    #pragma unroll
    for (int i = 0; i < 32; i += 8)
        g_eT[(size_t)(j0 + ty + i) * DIM + (d0 + tx)] = t[tx][ty + i];
}

// ============================================================
// Main HMMA kernel — R12 inner loop VERBATIM: 128 threads (4 warps),
// 32 rows/CTA, 1024 CTAs. Warp: m32 x distinct 2048-code quarter;
// B LDG-direct, 4-slot ring; 4 accumulator chains; norms subtracted
// in the epilogue (load covered by in-flight MMA latency).
// ============================================================
__global__ void __launch_bounds__(128, 2)
tc_argmin_kernel(const float* __restrict__ input) {
    __shared__ __align__(16) __half stage[8192];  // 16KB: 32-row A staging
    __shared__ float sbv[4][32];
    __shared__ float ssv[4][32];
    __shared__ int   sbi[4][32];

    const int tid  = threadIdx.x;
    const int wid  = tid >> 5;    // warp = code quarter
    const int lane = tid & 31;
    const int row0 = blockIdx.x * 32;
    const int mat  = lane >> 3;
    const int rr   = lane & 7;

    // ================= prologue: A fragments (both m16 tiles) ==============
    uint32_t areg[128];   // 2 m-tiles x 16 k16-chunks x 4
    {
        const int r = tid & 31;     // row
        const int p = tid >> 5;     // segment 0..3 (64 halves each)
        const float4* src = reinterpret_cast<const float4*>(
            input + (size_t)(row0 + r) * DIM + p * 64);
        #pragma unroll
        for (int u = 0; u < 8; ++u) {
            float4 fa = src[u * 2 + 0];
            float4 fb = src[u * 2 + 1];
            __half2 h0 = __floats2half2_rn(fa.x, fa.y);
            __half2 h1 = __floats2half2_rn(fa.z, fa.w);
            __half2 h2 = __floats2half2_rn(fb.x, fb.y);
            __half2 h3 = __floats2half2_rn(fb.z, fb.w);
            uint4 pk;
            pk.x = *reinterpret_cast<uint32_t*>(&h0);
            pk.y = *reinterpret_cast<uint32_t*>(&h1);
            pk.z = *reinterpret_cast<uint32_t*>(&h2);
            pk.w = *reinterpret_cast<uint32_t*>(&h3);
            int g = p * 4 * 2 + u;
            int swg = (g & 24) | ((g ^ r) & 7);
            *reinterpret_cast<uint4*>(
                reinterpret_cast<char*>(stage) + r * 512 + swg * 16) = pk;
        }
        __syncthreads();
        #pragma unroll
        for (int mt = 0; mt < 2; ++mt) {
            const int m = mt * 16 + (mat & 1) * 8 + rr;
            #pragma unroll
            for (int c = 0; c < 16; ++c) {
                int g = c * 2 + (mat >> 1);
                int swg = (g & 24) | ((g ^ rr) & 7);
                uint32_t addr = smem_u32(stage) + (uint32_t)(m * 512 + swg * 16);
                ldmx4(areg[mt * 64 + c * 4 + 0], areg[mt * 64 + c * 4 + 1],
                      areg[mt * 64 + c * 4 + 2], areg[mt * 64 + c * 4 + 3], addr);
            }
        }
    }

    // ================= main loop: LDG-direct B, 4 accumulator chains =======
    const uint4* bp = reinterpret_cast<const uint4*>(g_epk);
    const int q = wid;

    float bb[4] = {-3.0e38f, -3.0e38f, -3.0e38f, -3.0e38f};
    float ss[4] = {-3.0e38f, -3.0e38f, -3.0e38f, -3.0e38f};
    int   ii[4] = {0, 0, 0, 0};

    uint4 br[4];   // 4-slot ring, prefetch distance 4 g-steps
    {
        int id0 = q * 256;
        int b0 = ((id0 >> 3) * 64 + (id0 & 7)) * 32 + lane;
        #pragma unroll
        for (int g = 0; g < 4; ++g) br[g] = bp[b0 + g * 256];
    }

    #pragma unroll 1
    for (int u = 0; u < 256; ++u) {
        const int id    = q * 256 + u;
        const int base  = ((id >> 3) * 64 + (id & 7)) * 32 + lane;
        const int idn   = id + 1;
        const int basen = (u < 255) ? ((idn >> 3) * 64 + (idn & 7)) * 32 + lane : base;

        // 4 chains: [0..3]=m0 k-even, [4..7]=m0 k-odd, [8..11]=m1 k-even, [12..15]=m1 k-odd
        float creg[16];
        #pragma unroll
        for (int z = 0; z < 16; ++z) creg[z] = 0.f;

        #pragma unroll
        for (int g = 0; g < 8; ++g) {
            const uint4 b = br[g & 3];
            const int paddr = (g < 4) ? (base + (g + 4) * 256)
                                      : (basen + (g - 4) * 256);
            br[g & 3] = bp[paddr];
            mma16816(creg + 0,  areg + (2 * g) * 4,          b.x, b.y);  // m0 chain A
            mma16816(creg + 4,  areg + (2 * g + 1) * 4,      b.z, b.w);  // m0 chain B
            mma16816(creg + 8,  areg + 64 + (2 * g) * 4,     b.x, b.y);  // m1 chain A
            mma16816(creg + 12, areg + 64 + (2 * g + 1) * 4, b.z, b.w);  // m1 chain B
        }

        // epilogue: merge chains + subtract 0.5||e||^2 (covered by MMA latency)
        float2 c2 = __ldg(reinterpret_cast<const float2*>(g_c) + id * 4 + (lane & 3));
        int n0 = id * 8 + (lane & 3) * 2;
        float v;
        v = (creg[0] + creg[4]) - c2.x;
        if (v > bb[0]) { ss[0] = bb[0]; bb[0] = v; ii[0] = n0; } else if (v > ss[0]) ss[0] = v;
        v = (creg[1] + creg[5]) - c2.y;
        if (v > bb[0]) { ss[0] = bb[0]; bb[0] = v; ii[0] = n0 + 1; } else if (v > ss[0]) ss[0] = v;
        v = (creg[2] + creg[6]) - c2.x;
        if (v > bb[1]) { ss[1] = bb[1]; bb[1] = v; ii[1] = n0; } else if (v > ss[1]) ss[1] = v;
        v = (creg[3] + creg[7]) - c2.y;
        if (v > bb[1]) { ss[1] = bb[1]; bb[1] = v; ii[1] = n0 + 1; } else if (v > ss[1]) ss[1] = v;
        v = (creg[8] + creg[12]) - c2.x;
        if (v > bb[2]) { ss[2] = bb[2]; bb[2] = v; ii[2] = n0; } else if (v > ss[2]) ss[2] = v;
        v = (creg[9] + creg[13]) - c2.y;
        if (v > bb[2]) { ss[2] = bb[2]; bb[2] = v; ii[2] = n0 + 1; } else if (v > ss[2]) ss[2] = v;
        v = (creg[10] + creg[14]) - c2.x;
        if (v > bb[3]) { ss[3] = bb[3]; bb[3] = v; ii[3] = n0; } else if (v > ss[3]) ss[3] = v;
        v = (creg[11] + creg[15]) - c2.y;
        if (v > bb[3]) { ss[3] = bb[3]; bb[3] = v; ii[3] = n0 + 1; } else if (v > ss[3]) ss[3] = v;
    }

    // ================= reduction =================
    // quad merge within warp (lanes 0..3 of each quad hold different codes)
    #pragma unroll
    for (int sl = 0; sl < 4; ++sl) {
        float b2 = bb[sl], sec = ss[sl]; int i = ii[sl];
        #pragma unroll
        for (int off = 1; off <= 2; off <<= 1) {
            float ob = __shfl_xor_sync(0xffffffffu, b2, off);
            float os = __shfl_xor_sync(0xffffffffu, sec, off);
            int   oi = __shfl_xor_sync(0xffffffffu, i, off);
            if (ob > b2 || (ob == b2 && oi < i)) {
                sec = fmaxf(b2, os); b2 = ob; i = oi;
            } else {
                sec = fmaxf(sec, ob);
            }
        }
        if ((lane & 3) == 0) {
            int lrow = (sl >> 1) * 16 + (sl & 1) * 8 + (lane >> 2);
            sbv[wid][lrow] = b2;
            ssv[wid][lrow] = sec;
            sbi[wid][lrow] = i;
        }
    }
    __syncthreads();

    // merge 4 warps (disjoint code quarters) per row; write + flag
    if (tid < 32) {
        float va = sbv[0][tid], sa = ssv[0][tid];
        int   ia = sbi[0][tid];
        #pragma unroll
        for (int w = 1; w < 4; ++w) {
            float vb = sbv[w][tid], sb = ssv[w][tid];
            int   ib = sbi[w][tid];
            if (vb > va || (vb == va && ib < ia)) {
                sa = fmaxf(va, sb); va = vb; ia = ib;
            } else {
                sa = fmaxf(sa, vb);
            }
        }
        int row = row0 + tid;
        g_idx[row] = ia;
        if (va - sa < THRESH) {
            int sidx = atomicAdd(&g_nflag, 1);
            if (sidx < FLAG_CAP) { g_flag[sidx] = row; g_rkey[sidx] = 0ull; }
        }
    }
}

// ============================================================
// Exact fp32 rescue for narrow-margin rows.
// ============================================================
__device__ __forceinline__ unsigned long long score_key(float v, int j) {
    uint32_t u = __float_as_uint(v);
    u = (u & 0x80000000u) ? ~u : (u | 0x80000000u);
    return ((unsigned long long)u << 32) | (uint32_t)(0xFFFFFFFFu ^ (uint32_t)j);
}

__global__ void rescue_kernel(const float* __restrict__ input,
                              const float* __restrict__ embed) {
    __shared__ float xs[16][DIM];
    __shared__ unsigned long long wb[8][16];
    int nf = g_nflag; if (nf > FLAG_CAP) nf = FLAG_CAP;
    const int tid = threadIdx.x, wid = tid >> 5, lane = tid & 31;

    for (int base = blockIdx.y * 16; base < nf; base += 16 * 16) {
        int nrows = nf - base; if (nrows > 16) nrows = 16;
        __syncthreads();
        for (int i = tid; i < nrows * DIM; i += 256) {
            int r = i >> 8, d = i & 255;
            xs[r][d] = input[(size_t)g_flag[base + r] * DIM + d];
        }
        __syncthreads();

        int j0 = blockIdx.x * 1024 + tid;     // codes j0 + {0,256,512,768}
        float acc[4][16];
        #pragma unroll
        for (int qq = 0; qq < 4; ++qq)
            #pragma unroll
            for (int r = 0; r < 16; ++r) acc[qq][r] = 0.f;

        #pragma unroll 4
        for (int d = 0; d < DIM; ++d) {
            float e0 = embed[(size_t)d * NE + j0];
            float e1 = embed[(size_t)d * NE + j0 + 256];
            float e2 = embed[(size_t)d * NE + j0 + 512];
            float e3 = embed[(size_t)d * NE + j0 + 768];
            #pragma unroll
            for (int r = 0; r < 16; ++r) {
                float x = xs[r][d];
                acc[0][r] += e0 * x;
                acc[1][r] += e1 * x;
                acc[2][r] += e2 * x;
                acc[3][r] += e3 * x;
            }
        }
        float c0 = g_c[j0], c1 = g_c[j0 + 256], c2 = g_c[j0 + 512], c3 = g_c[j0 + 768];

        #pragma unroll 1
        for (int r = 0; r < 16; ++r) {
            float bv = acc[0][r] - c0; int bj = j0;
            float v1 = acc[1][r] - c1; if (v1 > bv) { bv = v1; bj = j0 + 256; }
            float v2 = acc[2][r] - c2; if (v2 > bv) { bv = v2; bj = j0 + 512; }
            float v3 = acc[3][r] - c3; if (v3 > bv) { bv = v3; bj = j0 + 768; }
            unsigned long long key = score_key(bv, bj);
            #pragma unroll
            for (int o = 16; o; o >>= 1) {
                unsigned long long other = __shfl_xor_sync(0xffffffffu, key, o);
                if (other > key) key = other;
            }
            if (lane == 0) wb[wid][r] = key;
        }
        __syncthreads();
        if (tid < nrows) {
            unsigned long long k = wb[0][tid];
            #pragma unroll
            for (int w = 1; w < 8; ++w) if (wb[w][tid] > k) k = wb[w][tid];
            atomicMax(&g_rkey[base + tid], k);
        }
    }
}

__global__ void extract_kernel() {
    int nf = g_nflag; if (nf > FLAG_CAP) nf = FLAG_CAP;
    for (int i = threadIdx.x; i < nf; i += 256) {
        unsigned long long k = g_rkey[i];
        g_idx[g_flag[i]] = (int)(0xFFFFFFFFu ^ (uint32_t)(k & 0xFFFFFFFFull));
    }
}

// ============================================================
// Output: gather, commitment loss, indices. 4 rows per warp (MLP on idx).
// ============================================================
__global__ void output_kernel(const float* __restrict__ input,
                              float* __restrict__ out, int write_extra) {
    int wid  = threadIdx.x >> 5;
    int lane = threadIdx.x & 31;
    int r0 = (blockIdx.x * 8 + wid) * 4;

    int j[4];
    #pragma unroll
    for (int k = 0; k < 4; ++k) j[k] = g_idx[r0 + k];

    float s = 0.f;
    #pragma unroll
    for (int k = 0; k < 4; ++k) {
        const float4* x4 = reinterpret_cast<const float4*>(input + (size_t)(r0 + k) * DIM);
        const float4* e4 = reinterpret_cast<const float4*>(g_eT + (size_t)j[k] * DIM);
        float4*       q4 = reinterpret_cast<float4*>(out + (size_t)(r0 + k) * DIM);
        #pragma unroll
        for (int t = 0; t < 2; ++t) {
            int d4 = lane + t * 32;
            float4 e = e4[d4];
            float4 x = x4[d4];
            q4[d4] = e;
            float a = e.x - x.x, b = e.y - x.y, c = e.z - x.z, d = e.w - x.w;
            s += a * a + b * b + c * c + d * d;
        }
    }
    #pragma unroll
    for (int o = 16; o; o >>= 1) s += __shfl_xor_sync(0xffffffffu, s, o);
    if (lane == 0) {
        atomicAdd(&g_diff, (double)s);
        if (write_extra) {
            #pragma unroll
            for (int k = 0; k < 4; ++k)
                out[(size_t)NROWS * DIM + 1 + r0 + k] = (float)j[k];
        }
    }
}

__global__ void finalize_kernel(float* __restrict__ out, int write_extra) {
    if (write_extra)
        out[(size_t)NROWS * DIM] = (float)(g_diff * (1.0 / ((double)NROWS * (double)DIM)));
}

// ============================================================
extern "C" void kernel_launch(void* const* d_in, const int* in_sizes, int n_in,
                              void* d_out, int out_size) {
    const float* input = (const float*)d_in[0];
    const float* embed = (const float*)d_in[1];
    if (in_sizes[0] == NE * DIM && in_sizes[1] == NROWS * DIM) {
        input = (const float*)d_in[1];
        embed = (const float*)d_in[0];
    }
    float* out = (float*)d_out;
    int write_extra = (out_size >= NROWS * DIM + 1 + NROWS) ? 1 : 0;

    norms_part_kernel<<<dim3(NE / 256, 4), 256>>>(embed);
    norms_comb_kernel<<<NE / 256, 256>>>();
    transpose_pack_kernel<<<dim3(NE / 32, DIM / 32), dim3(32, 8)>>>(embed);
    tc_argmin_kernel<<<NROWS / 32, 128>>>(input);
    rescue_kernel<<<dim3(8, 16), 256>>>(input, embed);
    extract_kernel<<<1, 256>>>();
    output_kernel<<<NROWS / 32, 256>>>(input, out, write_extra);
    finalize_kernel<<<1, 1>>>(out, write_extra);
}